// round 14
// baseline (speedup 1.0000x reference)
#include <cuda_runtime.h>
#include <cuda_fp16.h>
#include <cstdint>

#define BATCH 16384
#define NN    1024
#define EE    8
#define RR    64
#define ER    512
#define LL    3

// ---------------- static device scratch ----------------
__device__ float   g_xcur[BATCH * NN];
__device__ float   g_gates[BATCH * EE];          // layer-0 gates (softmaxed)
__device__ float   g_lpart[16][BATCH * EE];      // partial logits for next layer
__device__ __half  g_xh[BATCH * NN];             // x_l fp16
__device__ __half  g_cph[BATCH * ER];            // c' fp16
__device__ __half  g_Vh[LL * ER * NN];           // weights fp16
__device__ __half  g_Uh[LL * NN * ER];
__device__ __half  g_Ch[LL * EE * RR * RR];

// ---------------- helpers ----------------
__device__ __forceinline__ uint32_t smem_u32(const void* p) {
    uint32_t a;
    asm("{ .reg .u64 t; cvta.to.shared.u64 t, %1; cvt.u32.u64 %0, t; }" : "=r"(a) : "l"(p));
    return a;
}
__device__ __forceinline__ void ldsm4(uint32_t* r, uint32_t addr) {
    asm volatile("ldmatrix.sync.aligned.m8n8.x4.shared.b16 {%0,%1,%2,%3}, [%4];"
                 : "=r"(r[0]), "=r"(r[1]), "=r"(r[2]), "=r"(r[3]) : "r"(addr));
}
__device__ __forceinline__ void mma_f16(float* d, const uint32_t* a, const uint32_t* b) {
    asm volatile(
        "mma.sync.aligned.m16n8k16.row.col.f32.f16.f16.f32 "
        "{%0,%1,%2,%3}, {%4,%5,%6,%7}, {%8,%9}, {%0,%1,%2,%3};"
        : "+f"(d[0]), "+f"(d[1]), "+f"(d[2]), "+f"(d[3])
        : "r"(a[0]), "r"(a[1]), "r"(a[2]), "r"(a[3]), "r"(b[0]), "r"(b[1]));
}
__device__ __forceinline__ uint32_t hpack2(float a, float b) {
    __half ha = __float2half_rn(a), hb = __float2half_rn(b);
    return (uint32_t)__half_as_ushort(ha) | ((uint32_t)__half_as_ushort(hb) << 16);
}
__device__ __forceinline__ void cp16(uint32_t dst, const void* src) {
    asm volatile("cp.async.cg.shared.global [%0], [%1], 16;" :: "r"(dst), "l"(src));
}
#define CP_COMMIT() asm volatile("cp.async.commit_group;" ::: "memory")
#define CP_WAIT1()  asm volatile("cp.async.wait_group 1;" ::: "memory")
#define CP_WAIT0()  asm volatile("cp.async.wait_group 0;" ::: "memory")

// ---------------- prep kernels ----------------
__global__ void prep_x(const float* __restrict__ x) {
    int i = blockIdx.x * 256 + threadIdx.x;
    g_xh[i] = __float2half_rn(x[i]);
}
__global__ void prepVC_k(const float* __restrict__ V, const float* __restrict__ C) {
    int i = blockIdx.x * 256 + threadIdx.x;
    if (i < LL * ER * NN) g_Vh[i] = __float2half_rn(V[i]);
    int j = i - LL * ER * NN;
    if (j >= 0 && j < LL * EE * RR * RR) g_Ch[j] = __float2half_rn(C[j]);
}
__global__ void prepU_k(const float* __restrict__ U) {
    int o = blockIdx.x * 256 + threadIdx.x;     // o = (l*NN + n)*ER + er
    int er = o & 511, n = (o >> 9) & 1023, l = o >> 19;
    g_Uh[o] = __float2half_rn(U[(((size_t)(l * EE + (er >> 6))) * NN + n) * RR + (er & 63)]);
}

// ---------------- layer-0 gates (exact fp32) ----------------
__global__ void gates_k(const float* __restrict__ x_in, const float* __restrict__ gw) {
    int w = threadIdx.x >> 5, lane = threadIdx.x & 31;
    size_t row = (size_t)blockIdx.x * 8 + w;
    const float4* xr = (const float4*)(x_in + row * NN);
    float acc[EE];
#pragma unroll
    for (int e = 0; e < EE; e++) acc[e] = 0.f;
#pragma unroll
    for (int i = 0; i < 8; i++) {
        float4 xv = xr[i * 32 + lane];
#pragma unroll
        for (int e = 0; e < EE; e++) {
            float4 wv = ((const float4*)(gw + e * NN))[i * 32 + lane];
            acc[e] += xv.x * wv.x + xv.y * wv.y + xv.z * wv.z + xv.w * wv.w;
        }
    }
#pragma unroll
    for (int off = 16; off > 0; off >>= 1)
#pragma unroll
        for (int e = 0; e < EE; e++) acc[e] += __shfl_xor_sync(0xffffffffu, acc[e], off);
    if (lane == 0) {
        float m = acc[0];
#pragma unroll
        for (int e = 1; e < EE; e++) m = fmaxf(m, acc[e]);
        float s = 0.f, pe[EE];
#pragma unroll
        for (int e = 0; e < EE; e++) { pe[e] = __expf(acc[e] - m); s += pe[e]; }
        float inv = 1.0f / s;
#pragma unroll
        for (int e = 0; e < EE; e++) g_gates[row * EE + e] = pe[e] * inv;
    }
}

// ---------------- stage layout (bytes) ----------------
#define STG   36864
#define S_BH  18432
#define RV_H(el)  ((el) * 18432)
#define OCT       36864
#define SM_SZ     110592

__device__ __forceinline__ void stage_panels(
    uint32_t sbase, int t,
    const __half* A, int strideA, const __half* B, int strideB) {
    const int row = t >> 3;
    const uint32_t seg = (uint32_t)(t & 7) * 16;
#pragma unroll
    for (int it = 0; it < 4; it++) {
        int r = it * 32 + row;
        cp16(sbase + (uint32_t)r * 144 + seg, (const char*)(A + (size_t)r * strideA) + seg);
        cp16(sbase + S_BH + (uint32_t)r * 144 + seg,
             (const char*)(B + (size_t)r * strideB) + seg);
    }
}

__device__ __forceinline__ void mma_block128(uint32_t base, int wm, int wn, int lr, int kc,
                                             float d[2][8][4]) {
    const uint32_t Ah = base, Bh = base + S_BH;
#pragma unroll
    for (int q = 0; q < 4; q++) {
        uint32_t ah[2][4];
#pragma unroll
        for (int i = 0; i < 2; i++) {
            uint32_t ra = (uint32_t)((wm + i * 16 + lr) * 144 + (q * 16 + kc) * 2);
            ldsm4(ah[i], Ah + ra);
        }
        uint32_t bh[8][2];
#pragma unroll
        for (int jj = 0; jj < 4; jj++) {
            uint32_t rb = (uint32_t)((wn + jj * 16 + lr) * 144 + (q * 16 + kc) * 2);
            uint32_t tp[4];
            ldsm4(tp, Bh + rb);
            bh[2 * jj][0] = tp[0]; bh[2 * jj + 1][0] = tp[1];
            bh[2 * jj][1] = tp[2]; bh[2 * jj + 1][1] = tp[3];
        }
#pragma unroll
        for (int i = 0; i < 2; i++)
#pragma unroll
            for (int j = 0; j < 8; j++)
                mma_f16(d[i][j], ah[i], bh[j]);
    }
}

#define MAINLOOP(NK, pA, sA, pB, sB)                                          \
    stage_panels(sb, t, pA, sA, pB, sB); CP_COMMIT();                         \
    stage_panels(sb + STG, t, pA + 64, sA, pB + 64, sB); CP_COMMIT();         \
    _Pragma("unroll 1")                                                       \
    for (int kt = 0; kt < (NK); kt++) {                                       \
        if (kt + 1 < (NK)) { CP_WAIT1(); } else { CP_WAIT0(); }               \
        __syncthreads();                                                      \
        if (kt + 2 < (NK)) {                                                  \
            int bi = (kt + 2) % 3;                                            \
            stage_panels(sb + (uint32_t)bi * STG, t,                          \
                         pA + (kt + 2) * 64, sA, pB + (kt + 2) * 64, sB);     \
            CP_COMMIT();                                                      \
        }                                                                     \
        mma_block128(sb + (uint32_t)(kt % 3) * STG, wm, wn, lr, kc, d);       \
    }

// =====================================================================
// GEMM1 (v = x @ V^T) + fused expert chain -> c'
// grid (BATCH/128, 4), 256 threads, 2 CTAs/SM
// =====================================================================
__global__ void __launch_bounds__(256, 2) gemm1_k(int l) {
    extern __shared__ char smc[];
    const uint32_t sb = smem_u32(smc);
    const int t = threadIdx.x, w = t >> 5, lane = t & 31;
    const int lr = lane & 15, kc = (lane >> 4) * 8, g = lane >> 2, tig = lane & 3;
    const int wm = (w & 3) * 32, wn = (w >> 2) * 64;
    const size_t brow0 = (size_t)blockIdx.x * 128;

    const __half* pA = g_xh + brow0 * NN;
    const __half* pB = g_Vh + (size_t)l * ER * NN + (size_t)(blockIdx.y * 128) * NN;

    float d[2][8][4];
#pragma unroll
    for (int i = 0; i < 2; i++)
#pragma unroll
        for (int j = 0; j < 8; j++)
#pragma unroll
            for (int k = 0; k < 4; k++) d[i][j][k] = 0.f;

    MAINLOOP(16, pA, NN, pB, NN)
    __syncthreads();

    // ---- write relu(v) -> rv tiles ----
    const int el = w >> 2;
    {
#pragma unroll
        for (int i = 0; i < 2; i++) {
            int r0 = wm + i * 16 + g;
#pragma unroll
            for (int j = 0; j < 8; j++) {
                int c = j * 8 + 2 * tig;
                uint32_t h0 = hpack2(fmaxf(d[i][j][0], 0.f), fmaxf(d[i][j][1], 0.f));
                uint32_t h1 = hpack2(fmaxf(d[i][j][2], 0.f), fmaxf(d[i][j][3], 0.f));
                uint32_t o0 = (uint32_t)(r0 * 144 + c * 2);
                *(uint32_t*)(smc + RV_H(el) + o0)           = h0;
                *(uint32_t*)(smc + RV_H(el) + o0 + 8 * 144) = h1;
            }
        }
    }
    // ---- load C tiles (2 experts) ----
    {
        int el2 = t >> 7, r = (t >> 1) & 63, hf = t & 1;
        const __half* sH = g_Ch +
            (((size_t)(l * EE + blockIdx.y * 2 + el2)) * RR + r) * RR + hf * 32;
        char* dH = smc + OCT + el2 * 9216 + r * 144 + hf * 64;
#pragma unroll
        for (int s4 = 0; s4 < 4; s4++)
            *(uint4*)(dH + s4 * 16) = *(const uint4*)(sH + s4 * 8);
    }
    __syncthreads();

    // ---- expert mma: c = rv @ C_e^T  (K=64) ----
#pragma unroll
    for (int i = 0; i < 2; i++)
#pragma unroll
        for (int j = 0; j < 8; j++)
#pragma unroll
            for (int k = 0; k < 4; k++) d[i][j][k] = 0.f;
    {
        const uint32_t Ah = sb + RV_H(el);
        const uint32_t Bh = sb + OCT + el * 9216;
#pragma unroll
        for (int q = 0; q < 4; q++) {
            uint32_t ah[2][4];
#pragma unroll
            for (int i = 0; i < 2; i++) {
                uint32_t ra = (uint32_t)((wm + i * 16 + lr) * 144 + (q * 16 + kc) * 2);
                ldsm4(ah[i], Ah + ra);
            }
            uint32_t bh[8][2];
#pragma unroll
            for (int jj = 0; jj < 4; jj++) {
                uint32_t rb = (uint32_t)((jj * 16 + lr) * 144 + (q * 16 + kc) * 2);
                uint32_t tp[4];
                ldsm4(tp, Bh + rb);
                bh[2 * jj][0] = tp[0]; bh[2 * jj + 1][0] = tp[1];
                bh[2 * jj][1] = tp[2]; bh[2 * jj + 1][1] = tp[3];
            }
#pragma unroll
            for (int i = 0; i < 2; i++)
#pragma unroll
                for (int j = 0; j < 8; j++)
                    mma_f16(d[i][j], ah[i], bh[j]);
        }
    }

    // ---- epilogue: gates (l==0: precomputed; l>0: sum partials + softmax) ----
    {
        const int e = blockIdx.y * 2 + el;
#pragma unroll
        for (int i = 0; i < 2; i++) {
            size_t r0 = brow0 + wm + i * 16 + g, r1 = r0 + 8;
            float ga0, ga1;
            if (l == 0) {
                ga0 = g_gates[r0 * EE + e];
                ga1 = g_gates[r1 * EE + e];
            } else {
                ga0 = 0.f; ga1 = 0.f;
                if (tig == 0) {
                    float lg0[8], lg1[8];
#pragma unroll
                    for (int k = 0; k < 8; k++) { lg0[k] = 0.f; lg1[k] = 0.f; }
#pragma unroll
                    for (int s = 0; s < 16; s++) {
                        const float4* p0 = (const float4*)(g_lpart[s] + r0 * EE);
                        float4 a = p0[0], b = p0[1];
                        lg0[0] += a.x; lg0[1] += a.y; lg0[2] += a.z; lg0[3] += a.w;
                        lg0[4] += b.x; lg0[5] += b.y; lg0[6] += b.z; lg0[7] += b.w;
                        const float4* p1 = (const float4*)(g_lpart[s] + r1 * EE);
                        float4 c = p1[0], dd = p1[1];
                        lg1[0] += c.x; lg1[1] += c.y; lg1[2] += c.z; lg1[3] += c.w;
                        lg1[4] += dd.x; lg1[5] += dd.y; lg1[6] += dd.z; lg1[7] += dd.w;
                    }
                    float m0 = lg0[0], m1 = lg1[0];
#pragma unroll
                    for (int k = 1; k < 8; k++) { m0 = fmaxf(m0, lg0[k]); m1 = fmaxf(m1, lg1[k]); }
                    float s0 = 0.f, s1 = 0.f;
#pragma unroll
                    for (int k = 0; k < 8; k++) {
                        lg0[k] = __expf(lg0[k] - m0); s0 += lg0[k];
                        lg1[k] = __expf(lg1[k] - m1); s1 += lg1[k];
                    }
                    ga0 = lg0[e] / s0;
                    ga1 = lg1[e] / s1;
                }
                ga0 = __shfl_sync(0xffffffffu, ga0, lane & ~3);
                ga1 = __shfl_sync(0xffffffffu, ga1, lane & ~3);
            }
#pragma unroll
            for (int j = 0; j < 8; j++) {
                int cc = e * 64 + j * 8 + 2 * tig;
                *(uint32_t*)(g_cph + r0 * ER + cc) =
                    hpack2(ga0 * fmaxf(d[i][j][0], 0.f), ga0 * fmaxf(d[i][j][1], 0.f));
                *(uint32_t*)(g_cph + r1 * ER + cc) =
                    hpack2(ga1 * fmaxf(d[i][j][2], 0.f), ga1 * fmaxf(d[i][j][3], 0.f));
            }
        }
    }
}

// =====================================================================
// GEMM2: x_next = x0 * (c' @ U^T + bias) + x_l ; emits fp16 x_next
// and partial gate logits for the next layer.
// grid (BATCH/128, 8), 256 threads, 2 CTAs/SM
// =====================================================================
__global__ void __launch_bounds__(256, 2) gemm2_k(const float* __restrict__ x_in,
                                                  const float* __restrict__ biasg,
                                                  const float* __restrict__ gwg,
                                                  float* __restrict__ outg, int l) {
    extern __shared__ char smc[];
    const uint32_t sb = smem_u32(smc);
    const int t = threadIdx.x, w = t >> 5, lane = t & 31;
    const int lr = lane & 15, kc = (lane >> 4) * 8, g = lane >> 2, tig = lane & 3;
    const int wm = (w & 3) * 32, wn = (w >> 2) * 64;
    const size_t brow0 = (size_t)blockIdx.x * 128;
    const int no = blockIdx.y * 128;
    const int slice = blockIdx.y * 2 + (wn >> 6);

    const __half* pA = g_cph + brow0 * ER;
    const __half* pB = g_Uh + (size_t)l * NN * ER + (size_t)no * ER;

    float d[2][8][4];
#pragma unroll
    for (int i = 0; i < 2; i++)
#pragma unroll
        for (int j = 0; j < 8; j++)
#pragma unroll
            for (int k = 0; k < 4; k++) d[i][j][k] = 0.f;

    MAINLOOP(8, pA, ER, pB, ER)

    // ---- epilogue (fp32 residual path — exact) + partial logits ----
    const float* xl = l ? g_xcur : x_in;
    float* dst = (l == LL - 1) ? outg : g_xcur;
    const bool want_lg = (l < LL - 1);
#pragma unroll
    for (int i = 0; i < 2; i++) {
        size_t r0 = brow0 + wm + i * 16 + g, r1 = r0 + 8;
        float lg0[8], lg1[8];
#pragma unroll
        for (int k = 0; k < 8; k++) { lg0[k] = 0.f; lg1[k] = 0.f; }
#pragma unroll
        for (int j = 0; j < 8; j++) {
            int c0 = no + wn + j * 8 + 2 * tig;
            float2 bv = *(const float2*)(biasg + l * NN + c0);
            {
                float2 xv = *(const float2*)(x_in + r0 * NN + c0);
                float2 lv = *(const float2*)(xl + r0 * NN + c0);
                float o0 = fmaf(xv.x, d[i][j][0] + bv.x, lv.x);
                float o1 = fmaf(xv.y, d[i][j][1] + bv.y, lv.y);
                *(float2*)(dst + r0 * NN + c0) = make_float2(o0, o1);
                if (want_lg) {
                    *(uint32_t*)(g_xh + r0 * NN + c0) = hpack2(o0, o1);
#pragma unroll
                    for (int e = 0; e < EE; e++) {
                        float2 wv = *(const float2*)(gwg + e * NN + c0);
                        lg0[e] = fmaf(o0, wv.x, fmaf(o1, wv.y, lg0[e]));
                    }
                }
            }
            {
                float2 xv = *(const float2*)(x_in + r1 * NN + c0);
                float2 lv = *(const float2*)(xl + r1 * NN + c0);
                float o0 = fmaf(xv.x, d[i][j][2] + bv.x, lv.x);
                float o1 = fmaf(xv.y, d[i][j][3] + bv.y, lv.y);
                *(float2*)(dst + r1 * NN + c0) = make_float2(o0, o1);
                if (want_lg) {
                    *(uint32_t*)(g_xh + r1 * NN + c0) = hpack2(o0, o1);
#pragma unroll
                    for (int e = 0; e < EE; e++) {
                        float2 wv = *(const float2*)(gwg + e * NN + c0);
                        lg1[e] = fmaf(o0, wv.x, fmaf(o1, wv.y, lg1[e]));
                    }
                }
            }
        }
        if (want_lg) {
            // reduce over the 4 tig lanes sharing this row group
#pragma unroll
            for (int e = 0; e < EE; e++) {
                lg0[e] += __shfl_xor_sync(0xffffffffu, lg0[e], 1);
                lg0[e] += __shfl_xor_sync(0xffffffffu, lg0[e], 2);
                lg1[e] += __shfl_xor_sync(0xffffffffu, lg1[e], 1);
                lg1[e] += __shfl_xor_sync(0xffffffffu, lg1[e], 2);
            }
            if (tig == 0) {
#pragma unroll
                for (int e = 0; e < EE; e++) {
                    g_lpart[slice][r0 * EE + e] = lg0[e];
                    g_lpart[slice][r1 * EE + e] = lg1[e];
                }
            }
        }
    }
}

// =====================================================================
extern "C" void kernel_launch(void* const* d_in, const int* in_sizes, int n_in,
                              void* d_out, int out_size) {
    const float* x    = (const float*)d_in[0];
    const float* U    = (const float*)d_in[1];
    const float* V    = (const float*)d_in[2];
    const float* C    = (const float*)d_in[3];
    const float* bias = (const float*)d_in[4];
    const float* gw   = (const float*)d_in[5];
    float* out = (float*)d_out;

    cudaFuncSetAttribute(gemm1_k, cudaFuncAttributeMaxDynamicSharedMemorySize, SM_SZ);
    cudaFuncSetAttribute(gemm2_k, cudaFuncAttributeMaxDynamicSharedMemorySize, SM_SZ);

    const int VC_N = LL * ER * NN + LL * EE * RR * RR;
    // gemm1_k (layer 0) stays the 4th launch -> ncu profiles it.
    prep_x<<<BATCH * NN / 256, 256>>>(x);                       // 1
    prepVC_k<<<(VC_N + 255) / 256, 256>>>(V, C);                // 2
    gates_k<<<BATCH / 8, 256>>>(x, gw);                         // 3 (layer 0 only)
    gemm1_k<<<dim3(BATCH / 128, 4), 256, SM_SZ>>>(0);           // 4 <- profiled
    prepU_k<<<LL * NN * ER / 256, 256>>>(U);                    // 5
    gemm2_k<<<dim3(BATCH / 128, 8), 256, SM_SZ>>>(x, bias, gw, out, 0);
    for (int l = 1; l < LL; l++) {
        gemm1_k<<<dim3(BATCH / 128, 4), 256, SM_SZ>>>(l);
        gemm2_k<<<dim3(BATCH / 128, 8), 256, SM_SZ>>>(x, bias, gw, out, l);
    }
}

// round 15
// speedup vs baseline: 1.1164x; 1.1164x over previous
#include <cuda_runtime.h>
#include <cuda_fp16.h>
#include <cstdint>

#define BATCH 16384
#define NN    1024
#define EE    8
#define RR    64
#define ER    512
#define LL    3

// ---------------- static device scratch ----------------
__device__ float   g_xcur[BATCH * NN];
__device__ float   g_gates[BATCH * EE];
__device__ __half  g_xh[BATCH * NN];            // x_l fp16
__device__ __half  g_cph[BATCH * ER];           // c' fp16
__device__ __half  g_Vh[LL * ER * NN];          // weights fp16
__device__ __half  g_Uh[LL * NN * ER];
__device__ __half  g_Ch[LL * EE * RR * RR];

// ---------------- helpers ----------------
__device__ __forceinline__ uint32_t smem_u32(const void* p) {
    uint32_t a;
    asm("{ .reg .u64 t; cvta.to.shared.u64 t, %1; cvt.u32.u64 %0, t; }" : "=r"(a) : "l"(p));
    return a;
}
__device__ __forceinline__ void ldsm4(uint32_t* r, uint32_t addr) {
    asm volatile("ldmatrix.sync.aligned.m8n8.x4.shared.b16 {%0,%1,%2,%3}, [%4];"
                 : "=r"(r[0]), "=r"(r[1]), "=r"(r[2]), "=r"(r[3]) : "r"(addr));
}
__device__ __forceinline__ void mma_f16(float* d, const uint32_t* a, const uint32_t* b) {
    asm volatile(
        "mma.sync.aligned.m16n8k16.row.col.f32.f16.f16.f32 "
        "{%0,%1,%2,%3}, {%4,%5,%6,%7}, {%8,%9}, {%0,%1,%2,%3};"
        : "+f"(d[0]), "+f"(d[1]), "+f"(d[2]), "+f"(d[3])
        : "r"(a[0]), "r"(a[1]), "r"(a[2]), "r"(a[3]), "r"(b[0]), "r"(b[1]));
}
__device__ __forceinline__ uint32_t hpack2(float a, float b) {
    __half ha = __float2half_rn(a), hb = __float2half_rn(b);
    return (uint32_t)__half_as_ushort(ha) | ((uint32_t)__half_as_ushort(hb) << 16);
}
__device__ __forceinline__ void cp16(uint32_t dst, const void* src) {
    asm volatile("cp.async.cg.shared.global [%0], [%1], 16;" :: "r"(dst), "l"(src));
}
#define CP_COMMIT() asm volatile("cp.async.commit_group;" ::: "memory")
#define CP_WAIT1()  asm volatile("cp.async.wait_group 1;" ::: "memory")
#define CP_WAIT0()  asm volatile("cp.async.wait_group 0;" ::: "memory")

// ---------------- fused weight prep: V, C, U in one kernel ----------------
__global__ void prepAll_k(const float* __restrict__ V, const float* __restrict__ C,
                          const float* __restrict__ U) {
    int i = blockIdx.x * 256 + threadIdx.x;
    if (i < LL * ER * NN) {
        g_Vh[i] = __float2half_rn(V[i]);
        // U: same element count as V; permuted gather
        int er = i & 511, n = (i >> 9) & 1023, l = i >> 19;
        g_Uh[i] = __float2half_rn(
            U[(((size_t)(l * EE + (er >> 6))) * NN + n) * RR + (er & 63)]);
    }
    int j = i - LL * ER * NN;
    if (j >= 0 && j < LL * EE * RR * RR) g_Ch[j] = __float2half_rn(C[j]);
}

// ---------------- gates (exact fp32); l==0 also emits fp16 x ----------------
__global__ void gates_k(const float* __restrict__ x_in, const float* __restrict__ gw, int l) {
    const float* xl = l ? g_xcur : x_in;
    int w = threadIdx.x >> 5, lane = threadIdx.x & 31;
    size_t row = (size_t)blockIdx.x * 8 + w;
    const float4* xr = (const float4*)(xl + row * NN);
    float acc[EE];
#pragma unroll
    for (int e = 0; e < EE; e++) acc[e] = 0.f;
#pragma unroll
    for (int i = 0; i < 8; i++) {
        float4 xv = xr[i * 32 + lane];
        if (l == 0) {   // fused prep_x: emit fp16 copy of x0
            uint2 hx;
            hx.x = hpack2(xv.x, xv.y);
            hx.y = hpack2(xv.z, xv.w);
            *(uint2*)(g_xh + row * NN + (i * 32 + lane) * 4) = hx;
        }
#pragma unroll
        for (int e = 0; e < EE; e++) {
            float4 wv = ((const float4*)(gw + e * NN))[i * 32 + lane];
            acc[e] += xv.x * wv.x + xv.y * wv.y + xv.z * wv.z + xv.w * wv.w;
        }
    }
#pragma unroll
    for (int off = 16; off > 0; off >>= 1)
#pragma unroll
        for (int e = 0; e < EE; e++) acc[e] += __shfl_xor_sync(0xffffffffu, acc[e], off);
    if (lane == 0) {
        float m = acc[0];
#pragma unroll
        for (int e = 1; e < EE; e++) m = fmaxf(m, acc[e]);
        float s = 0.f, pe[EE];
#pragma unroll
        for (int e = 0; e < EE; e++) { pe[e] = __expf(acc[e] - m); s += pe[e]; }
        float inv = 1.0f / s;
#pragma unroll
        for (int e = 0; e < EE; e++) g_gates[row * EE + e] = pe[e] * inv;
    }
}

// ---------------- stage layout (bytes) ----------------
#define STG   36864
#define S_BH  18432
#define RV_H(el)  ((el) * 18432)
#define OCT       36864
#define SM_SZ     110592

__device__ __forceinline__ void stage_panels(
    uint32_t sbase, int t,
    const __half* A, int strideA, const __half* B, int strideB) {
    const int row = t >> 3;
    const uint32_t seg = (uint32_t)(t & 7) * 16;
#pragma unroll
    for (int it = 0; it < 4; it++) {
        int r = it * 32 + row;
        cp16(sbase + (uint32_t)r * 144 + seg, (const char*)(A + (size_t)r * strideA) + seg);
        cp16(sbase + S_BH + (uint32_t)r * 144 + seg,
             (const char*)(B + (size_t)r * strideB) + seg);
    }
}

__device__ __forceinline__ void mma_block128(uint32_t base, int wm, int wn, int lr, int kc,
                                             float d[2][8][4]) {
    const uint32_t Ah = base, Bh = base + S_BH;
#pragma unroll
    for (int q = 0; q < 4; q++) {
        uint32_t ah[2][4];
#pragma unroll
        for (int i = 0; i < 2; i++) {
            uint32_t ra = (uint32_t)((wm + i * 16 + lr) * 144 + (q * 16 + kc) * 2);
            ldsm4(ah[i], Ah + ra);
        }
        uint32_t bh[8][2];
#pragma unroll
        for (int jj = 0; jj < 4; jj++) {
            uint32_t rb = (uint32_t)((wn + jj * 16 + lr) * 144 + (q * 16 + kc) * 2);
            uint32_t tp[4];
            ldsm4(tp, Bh + rb);
            bh[2 * jj][0] = tp[0]; bh[2 * jj + 1][0] = tp[1];
            bh[2 * jj][1] = tp[2]; bh[2 * jj + 1][1] = tp[3];
        }
#pragma unroll
        for (int i = 0; i < 2; i++)
#pragma unroll
            for (int j = 0; j < 8; j++)
                mma_f16(d[i][j], ah[i], bh[j]);
    }
}

#define MAINLOOP(NK, pA, sA, pB, sB)                                          \
    stage_panels(sb, t, pA, sA, pB, sB); CP_COMMIT();                         \
    stage_panels(sb + STG, t, pA + 64, sA, pB + 64, sB); CP_COMMIT();         \
    _Pragma("unroll 1")                                                       \
    for (int kt = 0; kt < (NK); kt++) {                                       \
        if (kt + 1 < (NK)) { CP_WAIT1(); } else { CP_WAIT0(); }               \
        __syncthreads();                                                      \
        if (kt + 2 < (NK)) {                                                  \
            int bi = (kt + 2) % 3;                                            \
            stage_panels(sb + (uint32_t)bi * STG, t,                          \
                         pA + (kt + 2) * 64, sA, pB + (kt + 2) * 64, sB);     \
            CP_COMMIT();                                                      \
        }                                                                     \
        mma_block128(sb + (uint32_t)(kt % 3) * STG, wm, wn, lr, kc, d);       \
    }

// =====================================================================
// GEMM1 (v = x @ V^T) + fused expert chain -> c'
// grid (BATCH/128, 4), 256 threads, 2 CTAs/SM
// =====================================================================
__global__ void __launch_bounds__(256, 2) gemm1_k(int l) {
    extern __shared__ char smc[];
    const uint32_t sb = smem_u32(smc);
    const int t = threadIdx.x, w = t >> 5, lane = t & 31;
    const int lr = lane & 15, kc = (lane >> 4) * 8, g = lane >> 2, tig = lane & 3;
    const int wm = (w & 3) * 32, wn = (w >> 2) * 64;
    const size_t brow0 = (size_t)blockIdx.x * 128;

    const __half* pA = g_xh + brow0 * NN;
    const __half* pB = g_Vh + (size_t)l * ER * NN + (size_t)(blockIdx.y * 128) * NN;

    float d[2][8][4];
#pragma unroll
    for (int i = 0; i < 2; i++)
#pragma unroll
        for (int j = 0; j < 8; j++)
#pragma unroll
            for (int k = 0; k < 4; k++) d[i][j][k] = 0.f;

    MAINLOOP(16, pA, NN, pB, NN)
    __syncthreads();

    // ---- write relu(v) -> rv tiles (pitch 144, expert el = w>>2) ----
    const int el = w >> 2;
    {
#pragma unroll
        for (int i = 0; i < 2; i++) {
            int r0 = wm + i * 16 + g;
#pragma unroll
            for (int j = 0; j < 8; j++) {
                int c = j * 8 + 2 * tig;
                uint32_t h0 = hpack2(fmaxf(d[i][j][0], 0.f), fmaxf(d[i][j][1], 0.f));
                uint32_t h1 = hpack2(fmaxf(d[i][j][2], 0.f), fmaxf(d[i][j][3], 0.f));
                uint32_t o0 = (uint32_t)(r0 * 144 + c * 2);
                *(uint32_t*)(smc + RV_H(el) + o0)           = h0;
                *(uint32_t*)(smc + RV_H(el) + o0 + 8 * 144) = h1;
            }
        }
    }
    // ---- load C tiles (2 experts) ----
    {
        int el2 = t >> 7, r = (t >> 1) & 63, hf = t & 1;
        const __half* sH = g_Ch +
            (((size_t)(l * EE + blockIdx.y * 2 + el2)) * RR + r) * RR + hf * 32;
        char* dH = smc + OCT + el2 * 9216 + r * 144 + hf * 64;
#pragma unroll
        for (int s4 = 0; s4 < 4; s4++)
            *(uint4*)(dH + s4 * 16) = *(const uint4*)(sH + s4 * 8);
    }
    __syncthreads();

    // ---- expert mma: c = rv @ C_e^T  (K=64) ----
#pragma unroll
    for (int i = 0; i < 2; i++)
#pragma unroll
        for (int j = 0; j < 8; j++)
#pragma unroll
            for (int k = 0; k < 4; k++) d[i][j][k] = 0.f;
    {
        const uint32_t Ah = sb + RV_H(el);
        const uint32_t Bh = sb + OCT + el * 9216;
#pragma unroll
        for (int q = 0; q < 4; q++) {
            uint32_t ah[2][4];
#pragma unroll
            for (int i = 0; i < 2; i++) {
                uint32_t ra = (uint32_t)((wm + i * 16 + lr) * 144 + (q * 16 + kc) * 2);
                ldsm4(ah[i], Ah + ra);
            }
            uint32_t bh[8][2];
#pragma unroll
            for (int jj = 0; jj < 4; jj++) {
                uint32_t rb = (uint32_t)((jj * 16 + lr) * 144 + (q * 16 + kc) * 2);
                uint32_t tp[4];
                ldsm4(tp, Bh + rb);
                bh[2 * jj][0] = tp[0]; bh[2 * jj + 1][0] = tp[1];
                bh[2 * jj][1] = tp[2]; bh[2 * jj + 1][1] = tp[3];
            }
#pragma unroll
            for (int i = 0; i < 2; i++)
#pragma unroll
                for (int j = 0; j < 8; j++)
                    mma_f16(d[i][j], ah[i], bh[j]);
        }
    }

    // ---- epilogue: c' = gate*relu(c) -> global fp16 ----
    {
        const int e = blockIdx.y * 2 + el;
#pragma unroll
        for (int i = 0; i < 2; i++) {
            size_t r0 = brow0 + wm + i * 16 + g, r1 = r0 + 8;
            float g0 = g_gates[r0 * EE + e], g1 = g_gates[r1 * EE + e];
#pragma unroll
            for (int j = 0; j < 8; j++) {
                int cc = e * 64 + j * 8 + 2 * tig;
                *(uint32_t*)(g_cph + r0 * ER + cc) =
                    hpack2(g0 * fmaxf(d[i][j][0], 0.f), g0 * fmaxf(d[i][j][1], 0.f));
                *(uint32_t*)(g_cph + r1 * ER + cc) =
                    hpack2(g1 * fmaxf(d[i][j][2], 0.f), g1 * fmaxf(d[i][j][3], 0.f));
            }
        }
    }
}

// =====================================================================
// GEMM2: x_next = x0 * (c' @ U^T + bias) + x_l ; emits fp16 x_next
// grid (BATCH/128, 8), 256 threads, 2 CTAs/SM
// =====================================================================
__global__ void __launch_bounds__(256, 2) gemm2_k(const float* __restrict__ x_in,
                                                  const float* __restrict__ biasg,
                                                  float* __restrict__ outg, int l) {
    extern __shared__ char smc[];
    const uint32_t sb = smem_u32(smc);
    const int t = threadIdx.x, w = t >> 5, lane = t & 31;
    const int lr = lane & 15, kc = (lane >> 4) * 8, g = lane >> 2, tig = lane & 3;
    const int wm = (w & 3) * 32, wn = (w >> 2) * 64;
    const size_t brow0 = (size_t)blockIdx.x * 128;
    const int no = blockIdx.y * 128;

    const __half* pA = g_cph + brow0 * ER;
    const __half* pB = g_Uh + (size_t)l * NN * ER + (size_t)no * ER;

    float d[2][8][4];
#pragma unroll
    for (int i = 0; i < 2; i++)
#pragma unroll
        for (int j = 0; j < 8; j++)
#pragma unroll
            for (int k = 0; k < 4; k++) d[i][j][k] = 0.f;

    MAINLOOP(8, pA, ER, pB, ER)

    // ---- epilogue (fp32 residual path — exact) ----
    const float* xl = l ? g_xcur : x_in;
    float* dst = (l == LL - 1) ? outg : g_xcur;
#pragma unroll
    for (int i = 0; i < 2; i++) {
        size_t r0 = brow0 + wm + i * 16 + g, r1 = r0 + 8;
#pragma unroll
        for (int j = 0; j < 8; j++) {
            int c0 = no + wn + j * 8 + 2 * tig;
            float2 bv = *(const float2*)(biasg + l * NN + c0);
            {
                float2 xv = *(const float2*)(x_in + r0 * NN + c0);
                float2 lv = *(const float2*)(xl + r0 * NN + c0);
                float o0 = fmaf(xv.x, d[i][j][0] + bv.x, lv.x);
                float o1 = fmaf(xv.y, d[i][j][1] + bv.y, lv.y);
                *(float2*)(dst + r0 * NN + c0) = make_float2(o0, o1);
                if (l < LL - 1)
                    *(uint32_t*)(g_xh + r0 * NN + c0) = hpack2(o0, o1);
            }
            {
                float2 xv = *(const float2*)(x_in + r1 * NN + c0);
                float2 lv = *(const float2*)(xl + r1 * NN + c0);
                float o0 = fmaf(xv.x, d[i][j][2] + bv.x, lv.x);
                float o1 = fmaf(xv.y, d[i][j][3] + bv.y, lv.y);
                *(float2*)(dst + r1 * NN + c0) = make_float2(o0, o1);
                if (l < LL - 1)
                    *(uint32_t*)(g_xh + r1 * NN + c0) = hpack2(o0, o1);
            }
        }
    }
}

// =====================================================================
extern "C" void kernel_launch(void* const* d_in, const int* in_sizes, int n_in,
                              void* d_out, int out_size) {
    const float* x    = (const float*)d_in[0];
    const float* U    = (const float*)d_in[1];
    const float* V    = (const float*)d_in[2];
    const float* C    = (const float*)d_in[3];
    const float* bias = (const float*)d_in[4];
    const float* gw   = (const float*)d_in[5];
    float* out = (float*)d_out;

    cudaFuncSetAttribute(gemm1_k, cudaFuncAttributeMaxDynamicSharedMemorySize, SM_SZ);
    cudaFuncSetAttribute(gemm2_k, cudaFuncAttributeMaxDynamicSharedMemorySize, SM_SZ);

    const int PREP_N = LL * ER * NN + LL * EE * RR * RR;   // covers V/U range + C tail
    // Launch order: gemm2_k (layer 0) is the 4th launch -> ncu profiles it.
    prepAll_k<<<(PREP_N + 255) / 256, 256>>>(V, C, U);              // 1
    gates_k<<<BATCH / 8, 256>>>(x, gw, 0);                          // 2 (also emits g_xh)
    gemm1_k<<<dim3(BATCH / 128, 4), 256, SM_SZ>>>(0);               // 3
    gemm2_k<<<dim3(BATCH / 128, 8), 256, SM_SZ>>>(x, bias, out, 0); // 4 <- profiled
    for (int l = 1; l < LL; l++) {
        gates_k<<<BATCH / 8, 256>>>(x, gw, l);
        gemm1_k<<<dim3(BATCH / 128, 4), 256, SM_SZ>>>(l);
        gemm2_k<<<dim3(BATCH / 128, 8), 256, SM_SZ>>>(x, bias, out, l);
    }
}

// round 16
// speedup vs baseline: 1.1195x; 1.0028x over previous
#include <cuda_runtime.h>
#include <cuda_fp16.h>
#include <cstdint>

#define BATCH 16384
#define NN    1024
#define EE    8
#define RR    64
#define ER    512
#define LL    3

// ---------------- static device scratch ----------------
__device__ float   g_xcur[BATCH * NN];
__device__ float   g_gates[BATCH * EE];
__device__ __half  g_xh[BATCH * NN];            // x_l fp16
__device__ __half  g_cph[BATCH * ER];           // c' fp16
__device__ __half  g_Vh[LL * ER * NN];          // weights fp16
__device__ __half  g_Uh[LL * NN * ER];
__device__ __half  g_Ch[LL * EE * RR * RR];

// ---------------- helpers ----------------
__device__ __forceinline__ uint32_t smem_u32(const void* p) {
    uint32_t a;
    asm("{ .reg .u64 t; cvta.to.shared.u64 t, %1; cvt.u32.u64 %0, t; }" : "=r"(a) : "l"(p));
    return a;
}
__device__ __forceinline__ void ldsm4(uint32_t* r, uint32_t addr) {
    asm volatile("ldmatrix.sync.aligned.m8n8.x4.shared.b16 {%0,%1,%2,%3}, [%4];"
                 : "=r"(r[0]), "=r"(r[1]), "=r"(r[2]), "=r"(r[3]) : "r"(addr));
}
__device__ __forceinline__ void mma_f16(float* d, const uint32_t* a, const uint32_t* b) {
    asm volatile(
        "mma.sync.aligned.m16n8k16.row.col.f32.f16.f16.f32 "
        "{%0,%1,%2,%3}, {%4,%5,%6,%7}, {%8,%9}, {%0,%1,%2,%3};"
        : "+f"(d[0]), "+f"(d[1]), "+f"(d[2]), "+f"(d[3])
        : "r"(a[0]), "r"(a[1]), "r"(a[2]), "r"(a[3]), "r"(b[0]), "r"(b[1]));
}
__device__ __forceinline__ uint32_t hpack2(float a, float b) {
    __half ha = __float2half_rn(a), hb = __float2half_rn(b);
    return (uint32_t)__half_as_ushort(ha) | ((uint32_t)__half_as_ushort(hb) << 16);
}
__device__ __forceinline__ void cp16(uint32_t dst, const void* src) {
    asm volatile("cp.async.cg.shared.global [%0], [%1], 16;" :: "r"(dst), "l"(src));
}
__device__ __forceinline__ void pfl2(const void* p) {
    asm volatile("prefetch.global.L2 [%0];" :: "l"(p));
}
#define CP_COMMIT() asm volatile("cp.async.commit_group;" ::: "memory")
#define CP_WAIT1()  asm volatile("cp.async.wait_group 1;" ::: "memory")
#define CP_WAIT0()  asm volatile("cp.async.wait_group 0;" ::: "memory")

// ---------------- fused weight prep: V, C, U in one kernel ----------------
__global__ void prepAll_k(const float* __restrict__ V, const float* __restrict__ C,
                          const float* __restrict__ U) {
    int i = blockIdx.x * 256 + threadIdx.x;
    if (i < LL * ER * NN) {
        g_Vh[i] = __float2half_rn(V[i]);
        int er = i & 511, n = (i >> 9) & 1023, l = i >> 19;
        g_Uh[i] = __float2half_rn(
            U[(((size_t)(l * EE + (er >> 6))) * NN + n) * RR + (er & 63)]);
    }
    int j = i - LL * ER * NN;
    if (j >= 0 && j < LL * EE * RR * RR) g_Ch[j] = __float2half_rn(C[j]);
}

// ---------------- gates (exact fp32); l==0 also emits fp16 x ----------------
__global__ void gates_k(const float* __restrict__ x_in, const float* __restrict__ gw, int l) {
    const float* xl = l ? g_xcur : x_in;
    int w = threadIdx.x >> 5, lane = threadIdx.x & 31;
    size_t row = (size_t)blockIdx.x * 8 + w;
    const float4* xr = (const float4*)(xl + row * NN);
    float acc[EE];
#pragma unroll
    for (int e = 0; e < EE; e++) acc[e] = 0.f;
#pragma unroll
    for (int i = 0; i < 8; i++) {
        float4 xv = xr[i * 32 + lane];
        if (l == 0) {
            uint2 hx;
            hx.x = hpack2(xv.x, xv.y);
            hx.y = hpack2(xv.z, xv.w);
            *(uint2*)(g_xh + row * NN + (i * 32 + lane) * 4) = hx;
        }
#pragma unroll
        for (int e = 0; e < EE; e++) {
            float4 wv = ((const float4*)(gw + e * NN))[i * 32 + lane];
            acc[e] += xv.x * wv.x + xv.y * wv.y + xv.z * wv.z + xv.w * wv.w;
        }
    }
#pragma unroll
    for (int off = 16; off > 0; off >>= 1)
#pragma unroll
        for (int e = 0; e < EE; e++) acc[e] += __shfl_xor_sync(0xffffffffu, acc[e], off);
    if (lane == 0) {
        float m = acc[0];
#pragma unroll
        for (int e = 1; e < EE; e++) m = fmaxf(m, acc[e]);
        float s = 0.f, pe[EE];
#pragma unroll
        for (int e = 0; e < EE; e++) { pe[e] = __expf(acc[e] - m); s += pe[e]; }
        float inv = 1.0f / s;
#pragma unroll
        for (int e = 0; e < EE; e++) g_gates[row * EE + e] = pe[e] * inv;
    }
}

// ---------------- stage layout (bytes) ----------------
#define STG   36864
#define S_BH  18432
#define RV_H(el)  ((el) * 18432)
#define OCT       36864
#define SM_SZ     110592

__device__ __forceinline__ void stage_panels(
    uint32_t sbase, int t,
    const __half* A, int strideA, const __half* B, int strideB) {
    const int row = t >> 3;
    const uint32_t seg = (uint32_t)(t & 7) * 16;
#pragma unroll
    for (int it = 0; it < 4; it++) {
        int r = it * 32 + row;
        cp16(sbase + (uint32_t)r * 144 + seg, (const char*)(A + (size_t)r * strideA) + seg);
        cp16(sbase + S_BH + (uint32_t)r * 144 + seg,
             (const char*)(B + (size_t)r * strideB) + seg);
    }
}

__device__ __forceinline__ void mma_block128(uint32_t base, int wm, int wn, int lr, int kc,
                                             float d[2][8][4]) {
    const uint32_t Ah = base, Bh = base + S_BH;
#pragma unroll
    for (int q = 0; q < 4; q++) {
        uint32_t ah[2][4];
#pragma unroll
        for (int i = 0; i < 2; i++) {
            uint32_t ra = (uint32_t)((wm + i * 16 + lr) * 144 + (q * 16 + kc) * 2);
            ldsm4(ah[i], Ah + ra);
        }
        uint32_t bh[8][2];
#pragma unroll
        for (int jj = 0; jj < 4; jj++) {
            uint32_t rb = (uint32_t)((wn + jj * 16 + lr) * 144 + (q * 16 + kc) * 2);
            uint32_t tp[4];
            ldsm4(tp, Bh + rb);
            bh[2 * jj][0] = tp[0]; bh[2 * jj + 1][0] = tp[1];
            bh[2 * jj][1] = tp[2]; bh[2 * jj + 1][1] = tp[3];
        }
#pragma unroll
        for (int i = 0; i < 2; i++)
#pragma unroll
            for (int j = 0; j < 8; j++)
                mma_f16(d[i][j], ah[i], bh[j]);
    }
}

#define MAINLOOP(NK, pA, sA, pB, sB)                                          \
    stage_panels(sb, t, pA, sA, pB, sB); CP_COMMIT();                         \
    stage_panels(sb + STG, t, pA + 64, sA, pB + 64, sB); CP_COMMIT();         \
    _Pragma("unroll 1")                                                       \
    for (int kt = 0; kt < (NK); kt++) {                                       \
        if (kt + 1 < (NK)) { CP_WAIT1(); } else { CP_WAIT0(); }               \
        __syncthreads();                                                      \
        if (kt + 2 < (NK)) {                                                  \
            int bi = (kt + 2) % 3;                                            \
            stage_panels(sb + (uint32_t)bi * STG, t,                          \
                         pA + (kt + 2) * 64, sA, pB + (kt + 2) * 64, sB);     \
            CP_COMMIT();                                                      \
        }                                                                     \
        mma_block128(sb + (uint32_t)(kt % 3) * STG, wm, wn, lr, kc, d);       \
    }

// =====================================================================
// GEMM1 (v = x @ V^T) + fused expert chain -> c'
// grid (BATCH/128, 4), 256 threads, 2 CTAs/SM
// =====================================================================
__global__ void __launch_bounds__(256, 2) gemm1_k(int l) {
    extern __shared__ char smc[];
    const uint32_t sb = smem_u32(smc);
    const int t = threadIdx.x, w = t >> 5, lane = t & 31;
    const int lr = lane & 15, kc = (lane >> 4) * 8, g = lane >> 2, tig = lane & 3;
    const int wm = (w & 3) * 32, wn = (w >> 2) * 64;
    const size_t brow0 = (size_t)blockIdx.x * 128;

    const __half* pA = g_xh + brow0 * NN;
    const __half* pB = g_Vh + (size_t)l * ER * NN + (size_t)(blockIdx.y * 128) * NN;

    float d[2][8][4];
#pragma unroll
    for (int i = 0; i < 2; i++)
#pragma unroll
        for (int j = 0; j < 8; j++)
#pragma unroll
            for (int k = 0; k < 4; k++) d[i][j][k] = 0.f;

    MAINLOOP(16, pA, NN, pB, NN)

    // prefetch gate scalars into registers (latency hidden behind expert mma)
    const int el = w >> 2;
    const int e = blockIdx.y * 2 + el;
    float ga[2][2];
#pragma unroll
    for (int i = 0; i < 2; i++) {
        size_t r0 = brow0 + wm + i * 16 + g;
        ga[i][0] = g_gates[r0 * EE + e];
        ga[i][1] = g_gates[(r0 + 8) * EE + e];
    }
    __syncthreads();

    // ---- write relu(v) -> rv tiles (pitch 144, expert el = w>>2) ----
    {
#pragma unroll
        for (int i = 0; i < 2; i++) {
            int r0 = wm + i * 16 + g;
#pragma unroll
            for (int j = 0; j < 8; j++) {
                int c = j * 8 + 2 * tig;
                uint32_t h0 = hpack2(fmaxf(d[i][j][0], 0.f), fmaxf(d[i][j][1], 0.f));
                uint32_t h1 = hpack2(fmaxf(d[i][j][2], 0.f), fmaxf(d[i][j][3], 0.f));
                uint32_t o0 = (uint32_t)(r0 * 144 + c * 2);
                *(uint32_t*)(smc + RV_H(el) + o0)           = h0;
                *(uint32_t*)(smc + RV_H(el) + o0 + 8 * 144) = h1;
            }
        }
    }
    // ---- load C tiles (2 experts) ----
    {
        int el2 = t >> 7, r = (t >> 1) & 63, hf = t & 1;
        const __half* sH = g_Ch +
            (((size_t)(l * EE + blockIdx.y * 2 + el2)) * RR + r) * RR + hf * 32;
        char* dH = smc + OCT + el2 * 9216 + r * 144 + hf * 64;
#pragma unroll
        for (int s4 = 0; s4 < 4; s4++)
            *(uint4*)(dH + s4 * 16) = *(const uint4*)(sH + s4 * 8);
    }
    __syncthreads();

    // ---- expert mma: c = rv @ C_e^T  (K=64) ----
#pragma unroll
    for (int i = 0; i < 2; i++)
#pragma unroll
        for (int j = 0; j < 8; j++)
#pragma unroll
            for (int k = 0; k < 4; k++) d[i][j][k] = 0.f;
    {
        const uint32_t Ah = sb + RV_H(el);
        const uint32_t Bh = sb + OCT + el * 9216;
#pragma unroll
        for (int q = 0; q < 4; q++) {
            uint32_t ah[2][4];
#pragma unroll
            for (int i = 0; i < 2; i++) {
                uint32_t ra = (uint32_t)((wm + i * 16 + lr) * 144 + (q * 16 + kc) * 2);
                ldsm4(ah[i], Ah + ra);
            }
            uint32_t bh[8][2];
#pragma unroll
            for (int jj = 0; jj < 4; jj++) {
                uint32_t rb = (uint32_t)((jj * 16 + lr) * 144 + (q * 16 + kc) * 2);
                uint32_t tp[4];
                ldsm4(tp, Bh + rb);
                bh[2 * jj][0] = tp[0]; bh[2 * jj + 1][0] = tp[1];
                bh[2 * jj][1] = tp[2]; bh[2 * jj + 1][1] = tp[3];
            }
#pragma unroll
            for (int i = 0; i < 2; i++)
#pragma unroll
                for (int j = 0; j < 8; j++)
                    mma_f16(d[i][j], ah[i], bh[j]);
        }
    }

    // ---- epilogue: c' = gate*relu(c) -> global fp16 ----
    {
#pragma unroll
        for (int i = 0; i < 2; i++) {
            size_t r0 = brow0 + wm + i * 16 + g, r1 = r0 + 8;
#pragma unroll
            for (int j = 0; j < 8; j++) {
                int cc = e * 64 + j * 8 + 2 * tig;
                *(uint32_t*)(g_cph + r0 * ER + cc) =
                    hpack2(ga[i][0] * fmaxf(d[i][j][0], 0.f),
                           ga[i][0] * fmaxf(d[i][j][1], 0.f));
                *(uint32_t*)(g_cph + r1 * ER + cc) =
                    hpack2(ga[i][1] * fmaxf(d[i][j][2], 0.f),
                           ga[i][1] * fmaxf(d[i][j][3], 0.f));
            }
        }
    }
}

// =====================================================================
// GEMM2: x_next = x0 * (c' @ U^T + bias) + x_l ; emits fp16 x_next
// grid (BATCH/128, 8), 256 threads, 2 CTAs/SM
// =====================================================================
__global__ void __launch_bounds__(256, 2) gemm2_k(const float* __restrict__ x_in,
                                                  const float* __restrict__ biasg,
                                                  float* __restrict__ outg, int l) {
    extern __shared__ char smc[];
    const uint32_t sb = smem_u32(smc);
    const int t = threadIdx.x, w = t >> 5, lane = t & 31;
    const int lr = lane & 15, kc = (lane >> 4) * 8, g = lane >> 2, tig = lane & 3;
    const int wm = (w & 3) * 32, wn = (w >> 2) * 64;
    const size_t brow0 = (size_t)blockIdx.x * 128;
    const int no = blockIdx.y * 128;
    const float* xl = l ? g_xcur : x_in;

    // L2-prefetch epilogue operands; covered by the mainloop.
    {
        int r = t >> 1, half = t & 1;   // 128 rows x 2 halves (64 floats = 256B)
        const float* px = x_in + (brow0 + r) * NN + no + half * 64;
        pfl2(px); pfl2(px + 32);
        if (l) {
            const float* pl = xl + (brow0 + r) * NN + no + half * 64;
            pfl2(pl); pfl2(pl + 32);
        }
    }

    const __half* pA = g_cph + brow0 * ER;
    const __half* pB = g_Uh + (size_t)l * NN * ER + (size_t)no * ER;

    float d[2][8][4];
#pragma unroll
    for (int i = 0; i < 2; i++)
#pragma unroll
        for (int j = 0; j < 8; j++)
#pragma unroll
            for (int k = 0; k < 4; k++) d[i][j][k] = 0.f;

    MAINLOOP(8, pA, ER, pB, ER)

    // ---- epilogue (fp32 residual path — exact) ----
    float* dst = (l == LL - 1) ? outg : g_xcur;
#pragma unroll
    for (int i = 0; i < 2; i++) {
        size_t r0 = brow0 + wm + i * 16 + g, r1 = r0 + 8;
#pragma unroll
        for (int j = 0; j < 8; j++) {
            int c0 = no + wn + j * 8 + 2 * tig;
            float2 bv = *(const float2*)(biasg + l * NN + c0);
            {
                float2 xv = *(const float2*)(x_in + r0 * NN + c0);
                float2 lv = l ? *(const float2*)(xl + r0 * NN + c0) : xv;
                float o0 = fmaf(xv.x, d[i][j][0] + bv.x, lv.x);
                float o1 = fmaf(xv.y, d[i][j][1] + bv.y, lv.y);
                *(float2*)(dst + r0 * NN + c0) = make_float2(o0, o1);
                if (l < LL - 1)
                    *(uint32_t*)(g_xh + r0 * NN + c0) = hpack2(o0, o1);
            }
            {
                float2 xv = *(const float2*)(x_in + r1 * NN + c0);
                float2 lv = l ? *(const float2*)(xl + r1 * NN + c0) : xv;
                float o0 = fmaf(xv.x, d[i][j][2] + bv.x, lv.x);
                float o1 = fmaf(xv.y, d[i][j][3] + bv.y, lv.y);
                *(float2*)(dst + r1 * NN + c0) = make_float2(o0, o1);
                if (l < LL - 1)
                    *(uint32_t*)(g_xh + r1 * NN + c0) = hpack2(o0, o1);
            }
        }
    }
}

// =====================================================================
extern "C" void kernel_launch(void* const* d_in, const int* in_sizes, int n_in,
                              void* d_out, int out_size) {
    const float* x    = (const float*)d_in[0];
    const float* U    = (const float*)d_in[1];
    const float* V    = (const float*)d_in[2];
    const float* C    = (const float*)d_in[3];
    const float* bias = (const float*)d_in[4];
    const float* gw   = (const float*)d_in[5];
    float* out = (float*)d_out;

    cudaFuncSetAttribute(gemm1_k, cudaFuncAttributeMaxDynamicSharedMemorySize, SM_SZ);
    cudaFuncSetAttribute(gemm2_k, cudaFuncAttributeMaxDynamicSharedMemorySize, SM_SZ);

    const int PREP_N = LL * ER * NN + LL * EE * RR * RR;
    // Launch order: gemm2_k (layer 0) stays the 4th launch -> ncu profiles it.
    prepAll_k<<<(PREP_N + 255) / 256, 256>>>(V, C, U);              // 1
    gates_k<<<BATCH / 8, 256>>>(x, gw, 0);                          // 2 (emits g_xh)
    gemm1_k<<<dim3(BATCH / 128, 4), 256, SM_SZ>>>(0);               // 3
    gemm2_k<<<dim3(BATCH / 128, 8), 256, SM_SZ>>>(x, bias, out, 0); // 4 <- profiled
    for (int l = 1; l < LL; l++) {
        gates_k<<<BATCH / 8, 256>>>(x, gw, l);
        gemm1_k<<<dim3(BATCH / 128, 4), 256, SM_SZ>>>(l);
        gemm2_k<<<dim3(BATCH / 128, 8), 256, SM_SZ>>>(x, bias, out, l);
    }
}

// round 17
// speedup vs baseline: 1.1434x; 1.0213x over previous
#include <cuda_runtime.h>
#include <cuda_fp16.h>
#include <cstdint>

#define BATCH 16384
#define NN    1024
#define EE    8
#define RR    64
#define ER    512
#define LL    3

// ---------------- static device scratch ----------------
__device__ float   g_xcur[BATCH * NN];
__device__ float   g_gates[BATCH * EE];
__device__ __half  g_xh[BATCH * NN];            // x_l fp16
__device__ __half  g_cph[BATCH * ER];           // c' fp16
__device__ __half  g_Vh[LL * ER * NN];          // weights fp16
__device__ __half  g_Uh[LL * NN * ER];
__device__ __half  g_Ch[LL * EE * RR * RR];

// ---------------- helpers ----------------
__device__ __forceinline__ uint32_t smem_u32(const void* p) {
    uint32_t a;
    asm("{ .reg .u64 t; cvta.to.shared.u64 t, %1; cvt.u32.u64 %0, t; }" : "=r"(a) : "l"(p));
    return a;
}
__device__ __forceinline__ void ldsm4(uint32_t* r, uint32_t addr) {
    asm volatile("ldmatrix.sync.aligned.m8n8.x4.shared.b16 {%0,%1,%2,%3}, [%4];"
                 : "=r"(r[0]), "=r"(r[1]), "=r"(r[2]), "=r"(r[3]) : "r"(addr));
}
__device__ __forceinline__ void mma_f16(float* d, const uint32_t* a, const uint32_t* b) {
    asm volatile(
        "mma.sync.aligned.m16n8k16.row.col.f32.f16.f16.f32 "
        "{%0,%1,%2,%3}, {%4,%5,%6,%7}, {%8,%9}, {%0,%1,%2,%3};"
        : "+f"(d[0]), "+f"(d[1]), "+f"(d[2]), "+f"(d[3])
        : "r"(a[0]), "r"(a[1]), "r"(a[2]), "r"(a[3]), "r"(b[0]), "r"(b[1]));
}
__device__ __forceinline__ uint32_t hpack2(float a, float b) {
    __half ha = __float2half_rn(a), hb = __float2half_rn(b);
    return (uint32_t)__half_as_ushort(ha) | ((uint32_t)__half_as_ushort(hb) << 16);
}
__device__ __forceinline__ void cp16(uint32_t dst, const void* src) {
    asm volatile("cp.async.cg.shared.global [%0], [%1], 16;" :: "r"(dst), "l"(src));
}
__device__ __forceinline__ void pfl2(const void* p) {
    asm volatile("prefetch.global.L2 [%0];" :: "l"(p));
}
// PDL primitives (base sm_90 PTX; valid on sm_103 non-'a' target)
__device__ __forceinline__ void gdc_trigger() {
    asm volatile("griddepcontrol.launch_dependents;");
}
__device__ __forceinline__ void gdc_wait() {
    asm volatile("griddepcontrol.wait;" ::: "memory");
}
#define CP_COMMIT() asm volatile("cp.async.commit_group;" ::: "memory")
#define CP_WAIT1()  asm volatile("cp.async.wait_group 1;" ::: "memory")
#define CP_WAIT0()  asm volatile("cp.async.wait_group 0;" ::: "memory")

// ---------------- fused weight prep: V, C, U in one kernel ----------------
__global__ void prepAll_k(const float* __restrict__ V, const float* __restrict__ C,
                          const float* __restrict__ U) {
    gdc_trigger();   // lets gates(0) (independent) launch immediately
    int i = blockIdx.x * 256 + threadIdx.x;
    if (i < LL * ER * NN) {
        g_Vh[i] = __float2half_rn(V[i]);
        int er = i & 511, n = (i >> 9) & 1023, l = i >> 19;
        g_Uh[i] = __float2half_rn(
            U[(((size_t)(l * EE + (er >> 6))) * NN + n) * RR + (er & 63)]);
    }
    int j = i - LL * ER * NN;
    if (j >= 0 && j < LL * EE * RR * RR) g_Ch[j] = __float2half_rn(C[j]);
}

// ---------------- gates (exact fp32); l==0 also emits fp16 x ----------------
__global__ void gates_k(const float* __restrict__ x_in, const float* __restrict__ gw, int l) {
    if (l) gdc_trigger();   // l>=1: let gemm1(l) start its mainloop under us
    const float* xl = l ? g_xcur : x_in;
    int w = threadIdx.x >> 5, lane = threadIdx.x & 31;
    size_t row = (size_t)blockIdx.x * 8 + w;
    const float4* xr = (const float4*)(xl + row * NN);
    float acc[EE];
#pragma unroll
    for (int e = 0; e < EE; e++) acc[e] = 0.f;
#pragma unroll
    for (int i = 0; i < 8; i++) {
        float4 xv = xr[i * 32 + lane];
        if (l == 0) {
            uint2 hx;
            hx.x = hpack2(xv.x, xv.y);
            hx.y = hpack2(xv.z, xv.w);
            *(uint2*)(g_xh + row * NN + (i * 32 + lane) * 4) = hx;
        }
#pragma unroll
        for (int e = 0; e < EE; e++) {
            float4 wv = ((const float4*)(gw + e * NN))[i * 32 + lane];
            acc[e] += xv.x * wv.x + xv.y * wv.y + xv.z * wv.z + xv.w * wv.w;
        }
    }
#pragma unroll
    for (int off = 16; off > 0; off >>= 1)
#pragma unroll
        for (int e = 0; e < EE; e++) acc[e] += __shfl_xor_sync(0xffffffffu, acc[e], off);
    if (lane == 0) {
        float m = acc[0];
#pragma unroll
        for (int e = 1; e < EE; e++) m = fmaxf(m, acc[e]);
        float s = 0.f, pe[EE];
#pragma unroll
        for (int e = 0; e < EE; e++) { pe[e] = __expf(acc[e] - m); s += pe[e]; }
        float inv = 1.0f / s;
#pragma unroll
        for (int e = 0; e < EE; e++) g_gates[row * EE + e] = pe[e] * inv;
    }
}

// ---------------- stage layout (bytes) ----------------
#define STG   36864
#define S_BH  18432
#define RV_H(el)  ((el) * 18432)
#define OCT       36864
#define SM_SZ     110592

__device__ __forceinline__ void stage_panels(
    uint32_t sbase, int t,
    const __half* A, int strideA, const __half* B, int strideB) {
    const int row = t >> 3;
    const uint32_t seg = (uint32_t)(t & 7) * 16;
#pragma unroll
    for (int it = 0; it < 4; it++) {
        int r = it * 32 + row;
        cp16(sbase + (uint32_t)r * 144 + seg, (const char*)(A + (size_t)r * strideA) + seg);
        cp16(sbase + S_BH + (uint32_t)r * 144 + seg,
             (const char*)(B + (size_t)r * strideB) + seg);
    }
}

__device__ __forceinline__ void mma_block128(uint32_t base, int wm, int wn, int lr, int kc,
                                             float d[2][8][4]) {
    const uint32_t Ah = base, Bh = base + S_BH;
#pragma unroll
    for (int q = 0; q < 4; q++) {
        uint32_t ah[2][4];
#pragma unroll
        for (int i = 0; i < 2; i++) {
            uint32_t ra = (uint32_t)((wm + i * 16 + lr) * 144 + (q * 16 + kc) * 2);
            ldsm4(ah[i], Ah + ra);
        }
        uint32_t bh[8][2];
#pragma unroll
        for (int jj = 0; jj < 4; jj++) {
            uint32_t rb = (uint32_t)((wn + jj * 16 + lr) * 144 + (q * 16 + kc) * 2);
            uint32_t tp[4];
            ldsm4(tp, Bh + rb);
            bh[2 * jj][0] = tp[0]; bh[2 * jj + 1][0] = tp[1];
            bh[2 * jj][1] = tp[2]; bh[2 * jj + 1][1] = tp[3];
        }
#pragma unroll
        for (int i = 0; i < 2; i++)
#pragma unroll
            for (int j = 0; j < 8; j++)
                mma_f16(d[i][j], ah[i], bh[j]);
    }
}

#define MAINLOOP(NK, pA, sA, pB, sB)                                          \
    stage_panels(sb, t, pA, sA, pB, sB); CP_COMMIT();                         \
    stage_panels(sb + STG, t, pA + 64, sA, pB + 64, sB); CP_COMMIT();         \
    _Pragma("unroll 1")                                                       \
    for (int kt = 0; kt < (NK); kt++) {                                       \
        if (kt + 1 < (NK)) { CP_WAIT1(); } else { CP_WAIT0(); }               \
        __syncthreads();                                                      \
        if (kt + 2 < (NK)) {                                                  \
            int bi = (kt + 2) % 3;                                            \
            stage_panels(sb + (uint32_t)bi * STG, t,                          \
                         pA + (kt + 2) * 64, sA, pB + (kt + 2) * 64, sB);     \
            CP_COMMIT();                                                      \
        }                                                                     \
        mma_block128(sb + (uint32_t)(kt % 3) * STG, wm, wn, lr, kc, d);       \
    }

// =====================================================================
// GEMM1 (v = x @ V^T) + fused expert chain -> c'
// grid (BATCH/128, 4), 256 threads, 2 CTAs/SM
// For l>=1, launched with PDL: mainloop overlaps gates(l); gdc_wait()
// before the g_gates read.
// =====================================================================
__global__ void __launch_bounds__(256, 2) gemm1_k(int l) {
    extern __shared__ char smc[];
    const uint32_t sb = smem_u32(smc);
    const int t = threadIdx.x, w = t >> 5, lane = t & 31;
    const int lr = lane & 15, kc = (lane >> 4) * 8, g = lane >> 2, tig = lane & 3;
    const int wm = (w & 3) * 32, wn = (w >> 2) * 64;
    const size_t brow0 = (size_t)blockIdx.x * 128;

    const __half* pA = g_xh + brow0 * NN;
    const __half* pB = g_Vh + (size_t)l * ER * NN + (size_t)(blockIdx.y * 128) * NN;

    float d[2][8][4];
#pragma unroll
    for (int i = 0; i < 2; i++)
#pragma unroll
        for (int j = 0; j < 8; j++)
#pragma unroll
            for (int k = 0; k < 4; k++) d[i][j][k] = 0.f;

    MAINLOOP(16, pA, NN, pB, NN)

    // wait for gates(l) (no-op when not PDL-launched), then prefetch gates
    gdc_wait();
    const int el = w >> 2;
    const int e = blockIdx.y * 2 + el;
    float ga[2][2];
#pragma unroll
    for (int i = 0; i < 2; i++) {
        size_t r0 = brow0 + wm + i * 16 + g;
        ga[i][0] = g_gates[r0 * EE + e];
        ga[i][1] = g_gates[(r0 + 8) * EE + e];
    }
    __syncthreads();

    // ---- write relu(v) -> rv tiles (pitch 144, expert el = w>>2) ----
    {
#pragma unroll
        for (int i = 0; i < 2; i++) {
            int r0 = wm + i * 16 + g;
#pragma unroll
            for (int j = 0; j < 8; j++) {
                int c = j * 8 + 2 * tig;
                uint32_t h0 = hpack2(fmaxf(d[i][j][0], 0.f), fmaxf(d[i][j][1], 0.f));
                uint32_t h1 = hpack2(fmaxf(d[i][j][2], 0.f), fmaxf(d[i][j][3], 0.f));
                uint32_t o0 = (uint32_t)(r0 * 144 + c * 2);
                *(uint32_t*)(smc + RV_H(el) + o0)           = h0;
                *(uint32_t*)(smc + RV_H(el) + o0 + 8 * 144) = h1;
            }
        }
    }
    // ---- load C tiles (2 experts) ----
    {
        int el2 = t >> 7, r = (t >> 1) & 63, hf = t & 1;
        const __half* sH = g_Ch +
            (((size_t)(l * EE + blockIdx.y * 2 + el2)) * RR + r) * RR + hf * 32;
        char* dH = smc + OCT + el2 * 9216 + r * 144 + hf * 64;
#pragma unroll
        for (int s4 = 0; s4 < 4; s4++)
            *(uint4*)(dH + s4 * 16) = *(const uint4*)(sH + s4 * 8);
    }
    __syncthreads();

    // ---- expert mma: c = rv @ C_e^T  (K=64) ----
#pragma unroll
    for (int i = 0; i < 2; i++)
#pragma unroll
        for (int j = 0; j < 8; j++)
#pragma unroll
            for (int k = 0; k < 4; k++) d[i][j][k] = 0.f;
    {
        const uint32_t Ah = sb + RV_H(el);
        const uint32_t Bh = sb + OCT + el * 9216;
#pragma unroll
        for (int q = 0; q < 4; q++) {
            uint32_t ah[2][4];
#pragma unroll
            for (int i = 0; i < 2; i++) {
                uint32_t ra = (uint32_t)((wm + i * 16 + lr) * 144 + (q * 16 + kc) * 2);
                ldsm4(ah[i], Ah + ra);
            }
            uint32_t bh[8][2];
#pragma unroll
            for (int jj = 0; jj < 4; jj++) {
                uint32_t rb = (uint32_t)((jj * 16 + lr) * 144 + (q * 16 + kc) * 2);
                uint32_t tp[4];
                ldsm4(tp, Bh + rb);
                bh[2 * jj][0] = tp[0]; bh[2 * jj + 1][0] = tp[1];
                bh[2 * jj][1] = tp[2]; bh[2 * jj + 1][1] = tp[3];
            }
#pragma unroll
            for (int i = 0; i < 2; i++)
#pragma unroll
                for (int j = 0; j < 8; j++)
                    mma_f16(d[i][j], ah[i], bh[j]);
        }
    }

    // ---- epilogue: c' = gate*relu(c) -> global fp16 ----
    {
#pragma unroll
        for (int i = 0; i < 2; i++) {
            size_t r0 = brow0 + wm + i * 16 + g, r1 = r0 + 8;
#pragma unroll
            for (int j = 0; j < 8; j++) {
                int cc = e * 64 + j * 8 + 2 * tig;
                *(uint32_t*)(g_cph + r0 * ER + cc) =
                    hpack2(ga[i][0] * fmaxf(d[i][j][0], 0.f),
                           ga[i][0] * fmaxf(d[i][j][1], 0.f));
                *(uint32_t*)(g_cph + r1 * ER + cc) =
                    hpack2(ga[i][1] * fmaxf(d[i][j][2], 0.f),
                           ga[i][1] * fmaxf(d[i][j][3], 0.f));
            }
        }
    }
}

// =====================================================================
// GEMM2: x_next = x0 * (c' @ U^T + bias) + x_l ; emits fp16 x_next
// grid (BATCH/128, 8), 256 threads, 2 CTAs/SM
// =====================================================================
__global__ void __launch_bounds__(256, 2) gemm2_k(const float* __restrict__ x_in,
                                                  const float* __restrict__ biasg,
                                                  float* __restrict__ outg, int l) {
    extern __shared__ char smc[];
    const uint32_t sb = smem_u32(smc);
    const int t = threadIdx.x, w = t >> 5, lane = t & 31;
    const int lr = lane & 15, kc = (lane >> 4) * 8, g = lane >> 2, tig = lane & 3;
    const int wm = (w & 3) * 32, wn = (w >> 2) * 64;
    const size_t brow0 = (size_t)blockIdx.x * 128;
    const int no = blockIdx.y * 128;
    const float* xl = l ? g_xcur : x_in;

    // L2-prefetch epilogue operands; covered by the mainloop.
    {
        int r = t >> 1, half = t & 1;
        const float* px = x_in + (brow0 + r) * NN + no + half * 64;
        pfl2(px); pfl2(px + 32);
        if (l) {
            const float* pl = xl + (brow0 + r) * NN + no + half * 64;
            pfl2(pl); pfl2(pl + 32);
        }
    }

    const __half* pA = g_cph + brow0 * ER;
    const __half* pB = g_Uh + (size_t)l * NN * ER + (size_t)no * ER;

    float d[2][8][4];
#pragma unroll
    for (int i = 0; i < 2; i++)
#pragma unroll
        for (int j = 0; j < 8; j++)
#pragma unroll
            for (int k = 0; k < 4; k++) d[i][j][k] = 0.f;

    MAINLOOP(8, pA, ER, pB, ER)

    // ---- epilogue (fp32 residual path — exact) ----
    float* dst = (l == LL - 1) ? outg : g_xcur;
#pragma unroll
    for (int i = 0; i < 2; i++) {
        size_t r0 = brow0 + wm + i * 16 + g, r1 = r0 + 8;
#pragma unroll
        for (int j = 0; j < 8; j++) {
            int c0 = no + wn + j * 8 + 2 * tig;
            float2 bv = *(const float2*)(biasg + l * NN + c0);
            {
                float2 xv = *(const float2*)(x_in + r0 * NN + c0);
                float2 lv = l ? *(const float2*)(xl + r0 * NN + c0) : xv;
                float o0 = fmaf(xv.x, d[i][j][0] + bv.x, lv.x);
                float o1 = fmaf(xv.y, d[i][j][1] + bv.y, lv.y);
                *(float2*)(dst + r0 * NN + c0) = make_float2(o0, o1);
                if (l < LL - 1)
                    *(uint32_t*)(g_xh + r0 * NN + c0) = hpack2(o0, o1);
            }
            {
                float2 xv = *(const float2*)(x_in + r1 * NN + c0);
                float2 lv = l ? *(const float2*)(xl + r1 * NN + c0) : xv;
                float o0 = fmaf(xv.x, d[i][j][2] + bv.x, lv.x);
                float o1 = fmaf(xv.y, d[i][j][3] + bv.y, lv.y);
                *(float2*)(dst + r1 * NN + c0) = make_float2(o0, o1);
                if (l < LL - 1)
                    *(uint32_t*)(g_xh + r1 * NN + c0) = hpack2(o0, o1);
            }
        }
    }
}

// =====================================================================
static void launch_pdl(void* fn, dim3 grid, dim3 block, size_t smem,
                       void** args) {
    cudaLaunchConfig_t cfg = {};
    cfg.gridDim = grid;
    cfg.blockDim = block;
    cfg.dynamicSmemBytes = smem;
    cfg.stream = 0;
    cudaLaunchAttribute at[1];
    at[0].id = cudaLaunchAttributeProgrammaticStreamSerialization;
    at[0].val.programmaticStreamSerializationAllowed = 1;
    cfg.attrs = at;
    cfg.numAttrs = 1;
    cudaLaunchKernelExC(&cfg, fn, args);
}

extern "C" void kernel_launch(void* const* d_in, const int* in_sizes, int n_in,
                              void* d_out, int out_size) {
    const float* x    = (const float*)d_in[0];
    const float* U    = (const float*)d_in[1];
    const float* V    = (const float*)d_in[2];
    const float* C    = (const float*)d_in[3];
    const float* bias = (const float*)d_in[4];
    const float* gw   = (const float*)d_in[5];
    float* out = (float*)d_out;

    cudaFuncSetAttribute(gemm1_k, cudaFuncAttributeMaxDynamicSharedMemorySize, SM_SZ);
    cudaFuncSetAttribute(gemm2_k, cudaFuncAttributeMaxDynamicSharedMemorySize, SM_SZ);

    const int PREP_N = LL * ER * NN + LL * EE * RR * RR;
    // 1: prepAll (triggers at entry)
    prepAll_k<<<(PREP_N + 255) / 256, 256>>>(V, C, U);
    // 2: gates(0) — PDL: runs concurrently with prepAll (fully independent)
    {
        int l0 = 0;
        void* args[] = { (void*)&x, (void*)&gw, (void*)&l0 };
        launch_pdl((void*)gates_k, dim3(BATCH / 8), dim3(256), 0, args);
    }
    // 3: gemm1(0) — strict serial (needs g_xh + g_Vh + g_gates)
    gemm1_k<<<dim3(BATCH / 128, 4), 256, SM_SZ>>>(0);
    // 4: gemm2(0) <- profiled
    gemm2_k<<<dim3(BATCH / 128, 8), 256, SM_SZ>>>(x, bias, out, 0);
    for (int l = 1; l < LL; l++) {
        gates_k<<<BATCH / 8, 256>>>(x, gw, l);   // triggers at entry (l>0)
        {
            int ll = l;
            void* args[] = { (void*)&ll };
            launch_pdl((void*)gemm1_k, dim3(BATCH / 128, 4), dim3(256), SM_SZ, args);
        }
        gemm2_k<<<dim3(BATCH / 128, 8), 256, SM_SZ>>>(x, bias, out, l);
    }
}